// round 12
// baseline (speedup 1.0000x reference)
#include <cuda_runtime.h>
#include <cuda_bf16.h>
#include <cstdint>

#define UNITS 256
#define NUM_BUCKETS 501
#define LB (-17.0f)
#define UB (8.0f)
#define STEPF 0.05f
#define INV_STEP 20.0f
#define RESIDUE (-17.05f)
#define NLOG2E (-1.4426950408889634f)

// General-path table: per (unit, bucket):
//   .x = STEP * csum_exc[u][j] + RESIDUE + b[u]
//   .y = w[u][j] = relu(v[u][j])
__device__ float2 g_tab[UNITS * NUM_BUCKETS];

// Per-unit fast-path params (exp-domain folded):
//   if w[u,:] constant:  .x = -log2(e)*w (<= 0),  .y = -log2(e)*(w*(STEP-LB)+RESIDUE+b)
//   else:                .x = +1.0f (flag > 0), .y unused
__device__ float2 g_param[UNITS];

__device__ __forceinline__ float ex2f(float x) {
    float r;
    asm("ex2.approx.f32 %0, %1;" : "=f"(r) : "f"(x));
    return r;
}
__device__ __forceinline__ float rcpf(float x) {
    float r;
    asm("rcp.approx.f32 %0, %1;" : "=f"(r) : "f"(x));
    return r;
}

// ---------------------------------------------------------------------------
// Kernel A: per-unit param build; table built only for non-constant units.
// One block (512 threads) per unit.
// ---------------------------------------------------------------------------
__global__ void build_table_kernel(const float* __restrict__ v,
                                   const float* __restrict__ b) {
    const int u    = blockIdx.x;
    const int t    = threadIdx.x;
    const int lane = t & 31;
    const int warp = t >> 5;

    float w = 0.0f;
    if (t < NUM_BUCKETS) w = fmaxf(v[u * NUM_BUCKETS + t], 0.0f);

    // ---- min/max reduction (shuffle + smem) ----
    float mn = (t < NUM_BUCKETS) ? w :  1e30f;
    float mx = (t < NUM_BUCKETS) ? w : -1e30f;
    #pragma unroll
    for (int o = 16; o > 0; o >>= 1) {
        mn = fminf(mn, __shfl_xor_sync(0xffffffffu, mn, o));
        mx = fmaxf(mx, __shfl_xor_sync(0xffffffffu, mx, o));
    }
    __shared__ float smn[16], smx[16];
    __shared__ float result_mn, result_mx;
    if (lane == 0) { smn[warp] = mn; smx[warp] = mx; }
    __syncthreads();
    if (t == 0) {
        float a = smn[0], z = smx[0];
        #pragma unroll
        for (int i = 1; i < 16; ++i) { a = fminf(a, smn[i]); z = fmaxf(z, smx[i]); }
        result_mn = a; result_mx = z;
    }
    __syncthreads();

    const bool is_const = (result_mn == result_mx);
    const float bu = b[u];

    if (t == 0) {
        float2 p;
        if (is_const) {
            const float wc = result_mn;
            const float c  = fmaf(wc, STEPF - LB, RESIDUE + bu);
            p.x = NLOG2E * wc;    // <= 0
            p.y = NLOG2E * c;
        } else {
            p.x = 1.0f;           // flag: general path
            p.y = 0.0f;
        }
        g_param[u] = p;
    }
    if (is_const) return;   // uniform across block: skip scan + table write

    // ---- inclusive scan (shuffle within warp, then warp offsets) ----
    float val = w;
    #pragma unroll
    for (int o = 1; o < 32; o <<= 1) {
        float n = __shfl_up_sync(0xffffffffu, val, o);
        if (lane >= o) val += n;
    }
    __shared__ float wsum[16];
    if (lane == 31) wsum[warp] = val;
    __syncthreads();
    if (t == 0) {
        float acc = 0.0f;
        #pragma unroll
        for (int i = 0; i < 16; ++i) { float s0 = wsum[i]; wsum[i] = acc; acc += s0; }
    }
    __syncthreads();
    const float inc = val + wsum[warp];   // inclusive cumsum over buckets
    if (t < NUM_BUCKETS) {
        float exc = inc - w;
        float2 e;
        e.x = STEPF * exc + RESIDUE + bu;
        e.y = w;
        g_tab[u * NUM_BUCKETS + t] = e;
    }
}

// ---------------------------------------------------------------------------
// Kernel B: streaming main pass, thread-uniform fast/general split.
// Fast path: 4 front-batched loads (MLP_p1=4), then per sub-tile
// FFMA/EX2/FADD/RCP x4 + immediate evict-first store (keeps live regs low;
// __launch_bounds__(256,8) pins 8 CTA/SM). Default-policy loads keep x
// L2-resident across graph replays. Grid = one full wave (1184 CTAs).
// ---------------------------------------------------------------------------
__global__ void __launch_bounds__(256, 8)
iso_main_kernel(const float4* __restrict__ x4,
                float4* __restrict__ out4,
                int rows) {
    const int gid     = blockIdx.x * 256 + threadIdx.x;
    const int col     = gid & 63;                 // float4 column (0..63)
    const int row0    = gid >> 6;
    const int rstride = (gridDim.x * 256) >> 6;
    const int ubase   = col * 4;

    const float2 p0 = g_param[ubase + 0];
    const float2 p1 = g_param[ubase + 1];
    const float2 p2 = g_param[ubase + 2];
    const float2 p3 = g_param[ubase + 3];

    const float4* __restrict__ pin  = x4   + (size_t)row0 * 64 + col;
    float4* __restrict__       pout = out4 + (size_t)row0 * 64 + col;
    const int step = rstride * 64;

    const bool fast = (p0.x <= 0.0f) & (p1.x <= 0.0f) &
                      (p2.x <= 0.0f) & (p3.x <= 0.0f);

    if (fast) {
        const float nw[4] = {p0.x, p1.x, p2.x, p3.x};
        const float nc[4] = {p0.y, p1.y, p2.y, p3.y};
        int row = row0;
        // 4 loads in flight; compute + store immediately per sub-tile
        for (; row + 3 * rstride < rows; row += 4 * rstride) {
            float4 x0 = pin[0];
            float4 x1 = pin[step];
            float4 x2 = pin[2 * step];
            float4 x3 = pin[3 * step];

            x0.x = rcpf(1.0f + ex2f(fmaf(x0.x, nw[0], nc[0])));
            x0.y = rcpf(1.0f + ex2f(fmaf(x0.y, nw[1], nc[1])));
            x0.z = rcpf(1.0f + ex2f(fmaf(x0.z, nw[2], nc[2])));
            x0.w = rcpf(1.0f + ex2f(fmaf(x0.w, nw[3], nc[3])));
            __stcs(pout, x0);

            x1.x = rcpf(1.0f + ex2f(fmaf(x1.x, nw[0], nc[0])));
            x1.y = rcpf(1.0f + ex2f(fmaf(x1.y, nw[1], nc[1])));
            x1.z = rcpf(1.0f + ex2f(fmaf(x1.z, nw[2], nc[2])));
            x1.w = rcpf(1.0f + ex2f(fmaf(x1.w, nw[3], nc[3])));
            __stcs(pout + step, x1);

            x2.x = rcpf(1.0f + ex2f(fmaf(x2.x, nw[0], nc[0])));
            x2.y = rcpf(1.0f + ex2f(fmaf(x2.y, nw[1], nc[1])));
            x2.z = rcpf(1.0f + ex2f(fmaf(x2.z, nw[2], nc[2])));
            x2.w = rcpf(1.0f + ex2f(fmaf(x2.w, nw[3], nc[3])));
            __stcs(pout + 2 * step, x2);

            x3.x = rcpf(1.0f + ex2f(fmaf(x3.x, nw[0], nc[0])));
            x3.y = rcpf(1.0f + ex2f(fmaf(x3.y, nw[1], nc[1])));
            x3.z = rcpf(1.0f + ex2f(fmaf(x3.z, nw[2], nc[2])));
            x3.w = rcpf(1.0f + ex2f(fmaf(x3.w, nw[3], nc[3])));
            __stcs(pout + 3 * step, x3);

            pin  += 4 * step;
            pout += 4 * step;
        }
        // tail
        for (; row < rows; row += rstride) {
            float4 xa = *pin;
            xa.x = rcpf(1.0f + ex2f(fmaf(xa.x, nw[0], nc[0])));
            xa.y = rcpf(1.0f + ex2f(fmaf(xa.y, nw[1], nc[1])));
            xa.z = rcpf(1.0f + ex2f(fmaf(xa.z, nw[2], nc[2])));
            xa.w = rcpf(1.0f + ex2f(fmaf(xa.w, nw[3], nc[3])));
            __stcs(pout, xa);
            pin  += step;
            pout += step;
        }
    } else {
        for (int row = row0; row < rows; row += rstride) {
            const float4 xv = *pin;
            float xin[4] = {xv.x, xv.y, xv.z, xv.w};
            float oo[4];
            #pragma unroll
            for (int j = 0; j < 4; ++j) {
                const float xc = fminf(fmaxf(xin[j], LB + 1e-9f), UB - 1e-9f);
                const float2 pj = (j == 0) ? p0 : (j == 1) ? p1 : (j == 2) ? p2 : p3;
                if (pj.x <= 0.0f) {
                    oo[j] = rcpf(1.0f + ex2f(fmaf(xc, pj.x, pj.y)));
                } else {
                    float t = xc - LB + STEPF;            // in (0.05, 25.05)
                    int idx = (int)(t * INV_STEP);
                    idx = min(idx, NUM_BUCKETS - 1);
                    float delta = t - (float)idx * STEPF;
                    float2 tw = __ldg(&g_tab[(ubase + j) * NUM_BUCKETS + idx]);
                    float logit = fmaf(delta, tw.y, tw.x);
                    oo[j] = rcpf(1.0f + ex2f(NLOG2E * logit));
                }
            }
            __stcs(pout, make_float4(oo[0], oo[1], oo[2], oo[3]));
            pin  += step;
            pout += step;
        }
    }
}

// ---------------------------------------------------------------------------
extern "C" void kernel_launch(void* const* d_in, const int* in_sizes, int n_in,
                              void* d_out, int out_size) {
    const float* x = (const float*)d_in[0];   // (65536, 256)
    const float* v = (const float*)d_in[1];   // (256, 501)
    const float* b = (const float*)d_in[2];   // (256,)
    float* out = (float*)d_out;

    build_table_kernel<<<UNITS, 512>>>(v, b);

    const int total = in_sizes[0];            // 65536 * 256
    const int rows  = total / UNITS;          // 65536

    // One full wave: 148 SMs x 8 resident CTAs (256 thr, 32 regs) = 1184
    const int blocks = 1184;
    iso_main_kernel<<<blocks, 256>>>((const float4*)x, (float4*)out, rows);
}